// round 9
// baseline (speedup 1.0000x reference)
#include <cuda_runtime.h>
#include <math.h>

#define TS 2048
#define ESTR 128
#define oA 0
#define oB 36
#define oC 42
#define oE 78
#define oJ 84
#define LOG2PI 1.8378770664093454836

__device__ double g_buf[2][TS*ESTR];
__device__ double g_llp[16];

__device__ __forceinline__ double inv4d(const double A[4][4], double R[4][4]) {
    double a00=A[0][0],a01=A[0][1],a02=A[0][2],a03=A[0][3];
    double a10=A[1][0],a11=A[1][1],a12=A[1][2],a13=A[1][3];
    double a20=A[2][0],a21=A[2][1],a22=A[2][2],a23=A[2][3];
    double a30=A[3][0],a31=A[3][1],a32=A[3][2],a33=A[3][3];
    double s0=a00*a11-a10*a01,s1=a00*a12-a10*a02,s2=a00*a13-a10*a03;
    double s3=a01*a12-a11*a02,s4=a01*a13-a11*a03,s5=a02*a13-a12*a03;
    double c5=a22*a33-a32*a23,c4=a21*a33-a31*a23,c3=a21*a32-a31*a22;
    double c2=a20*a33-a30*a23,c1=a20*a32-a30*a22,c0=a20*a31-a30*a21;
    double det=s0*c5-s1*c4+s2*c3+s3*c2-s4*c1+s5*c0;
    double id=1.0/det;
    R[0][0]=( a11*c5-a12*c4+a13*c3)*id; R[0][1]=(-a01*c5+a02*c4-a03*c3)*id;
    R[0][2]=( a31*s5-a32*s4+a33*s3)*id; R[0][3]=(-a21*s5+a22*s4-a23*s3)*id;
    R[1][0]=(-a10*c5+a12*c2-a13*c1)*id; R[1][1]=( a00*c5-a02*c2+a03*c1)*id;
    R[1][2]=(-a30*s5+a32*s2-a33*s1)*id; R[1][3]=( a20*s5-a22*s2+a23*s1)*id;
    R[2][0]=( a10*c4-a11*c2+a13*c0)*id; R[2][1]=(-a00*c4+a01*c2-a03*c0)*id;
    R[2][2]=( a30*s4-a31*s2+a33*s0)*id; R[2][3]=(-a20*s4+a21*s2-a23*s0)*id;
    R[3][0]=(-a10*c3+a11*c1-a12*c0)*id; R[3][1]=( a00*c3-a01*c1+a02*c0)*id;
    R[3][2]=(-a30*s3+a31*s1-a32*s0)*id; R[3][3]=( a20*s3-a21*s1+a22*s0)*id;
    return det;
}

__device__ void inv6d(const double* N, double* D) {
    double M[6][12];
    for (int r=0;r<6;++r){ for(int c=0;c<6;++c){ M[r][c]=N[r*6+c]; M[r][6+c]=(r==c)?1.0:0.0; } }
    for (int col=0;col<6;++col){
        int p=col; double best=fabs(M[col][col]);
        for (int r=col+1;r<6;++r){ double v=fabs(M[r][col]); if(v>best){best=v;p=r;} }
        if (p!=col) for (int j=0;j<12;++j){ double t=M[col][j]; M[col][j]=M[p][j]; M[p][j]=t; }
        double pi=1.0/M[col][col];
        for (int j=0;j<12;++j) M[col][j]*=pi;
        for (int r=0;r<6;++r){ if(r==col)continue; double f=M[r][col];
            for (int j=0;j<12;++j) M[r][j]-=f*M[col][j]; }
    }
    for (int r=0;r<6;++r) for (int c=0;c<6;++c) D[r*6+c]=M[r][6+c];
}

// Sarkka filtering composition: ei earlier, ej later.
__device__ void compose(const double* __restrict__ ei, const double* __restrict__ ej,
                        double* __restrict__ eo) {
    double D[36];
    {
        double N[36];
        for (int r=0;r<6;++r) for (int c=0;c<6;++c){
            double s=(r==c)?1.0:0.0;
            for (int k=0;k<6;++k) s+=ei[oC+r*6+k]*ej[oJ+k*6+c];
            N[r*6+c]=s;
        }
        inv6d(N,D);
    }
    double T1[36];
    for (int r=0;r<6;++r) for (int c=0;c<6;++c){
        double s=0; for (int k=0;k<6;++k) s+=D[r*6+k]*ei[oA+k*6+c];
        T1[r*6+c]=s;
    }
    for (int r=0;r<6;++r) for (int c=0;c<6;++c){
        double s=0; for (int k=0;k<6;++k) s+=ej[oA+r*6+k]*T1[k*6+c];
        eo[oA+r*6+c]=s;
    }
    {
        double u[6],w[6];
        for (int r=0;r<6;++r){ double s=ei[oB+r];
            for (int k=0;k<6;++k) s+=ei[oC+r*6+k]*ej[oE+k]; u[r]=s; }
        for (int r=0;r<6;++r){ double s=0;
            for (int k=0;k<6;++k) s+=D[r*6+k]*u[k]; w[r]=s; }
        for (int r=0;r<6;++r){ double s=ej[oB+r];
            for (int k=0;k<6;++k) s+=ej[oA+r*6+k]*w[k]; eo[oB+r]=s; }
    }
    {
        double T3[36],T4[36];
        for (int r=0;r<6;++r) for (int c=0;c<6;++c){
            double s=0; for (int k=0;k<6;++k) s+=D[r*6+k]*ei[oC+k*6+c];
            T3[r*6+c]=s;
        }
        for (int r=0;r<6;++r) for (int c=0;c<6;++c){
            double s=0; for (int k=0;k<6;++k) s+=ej[oA+r*6+k]*T3[k*6+c];
            T4[r*6+c]=s;
        }
        for (int r=0;r<6;++r) for (int c=0;c<6;++c){
            double s=ej[oC+r*6+c];
            for (int k=0;k<6;++k) s+=T4[r*6+k]*ej[oA+c*6+k];
            eo[oC+r*6+c]=s;
        }
        for (int r=0;r<6;++r) for (int c=r+1;c<6;++c){
            double m=0.5*(eo[oC+r*6+c]+eo[oC+c*6+r]);
            eo[oC+r*6+c]=m; eo[oC+c*6+r]=m;
        }
    }
    {
        double rv[6];
        for (int r=0;r<6;++r){ double s=ej[oE+r];
            for (int k=0;k<6;++k) s-=ej[oJ+r*6+k]*ei[oB+k]; rv[r]=s; }
        for (int c=0;c<6;++c){ double s=ei[oE+c];
            for (int k=0;k<6;++k) s+=T1[k*6+c]*rv[k]; eo[oE+c]=s; }
    }
    {
        double T5[36];
        for (int r=0;r<6;++r) for (int c=0;c<6;++c){
            double s=0; for (int k=0;k<6;++k) s+=ej[oJ+r*6+k]*ei[oA+k*6+c];
            T5[r*6+c]=s;
        }
        for (int r=0;r<6;++r) for (int c=0;c<6;++c){
            double s=ei[oJ+r*6+c];
            for (int k=0;k<6;++k) s+=T1[k*6+r]*T5[k*6+c];
            eo[oJ+r*6+c]=s;
        }
        for (int r=0;r<6;++r) for (int c=r+1;c<6;++c){
            double m=0.5*(eo[oJ+r*6+c]+eo[oJ+c*6+r]);
            eo[oJ+r*6+c]=m; eo[oJ+c*6+r]=m;
        }
    }
}

__global__ void init_elems(const float* __restrict__ track, const float* __restrict__ bs,
                           const float* __restrict__ onp, const float* __restrict__ tnp) {
    int t = blockIdx.x*blockDim.x + threadIdx.x;
    if (t >= TS) return;
    double* e = &g_buf[0][t*ESTR];
    const double sig2 = (double)onp[0]*(double)onp[0];
    const double q = (double)tnp[0]*(double)tnp[0];
    const double rn = sig2/32.0;
    double Qs[2][2] = {{q/3.0, q*0.5},{q*0.5, q}};
    double y0 = (double)track[2*t], y1 = (double)track[2*t+1];
    double yb[4] = {y0,y1,y0,y1};
    if (t == 0) {
        double P[6][6];
        for (int r=0;r<6;++r) for (int c=0;c<6;++c) P[r][c]=0.0;
        P[0][0]=(double)bs[0]/32.0; P[1][1]=(double)bs[1]/32.0;
        P[2][2]=P[0][0]; P[3][3]=P[1][1];
        P[4][4]=2.0+Qs[0][0]; P[4][5]=1.0+Qs[0][1];
        P[5][4]=1.0+Qs[1][0]; P[5][5]=1.0+Qs[1][1];
        double PH[6][4];
        for (int r=0;r<6;++r) for (int g=0;g<4;++g) PH[r][g]=P[r][g]+P[r][4+(g>>1)];
        double S4[4][4];
        for (int g=0;g<4;++g) for (int h=0;h<4;++h)
            S4[g][h]=PH[g][h]+PH[4+(g>>1)][h]+((g==h)?rn:0.0);
        double Si[4][4]; inv4d(S4,Si);
        double K[6][4];
        for (int r=0;r<6;++r) for (int g=0;g<4;++g){
            double s=0; for (int h=0;h<4;++h) s+=PH[r][h]*Si[h][g]; K[r][g]=s; }
        for (int i=0;i<36;++i) e[oA+i]=0.0;
        for (int r=0;r<6;++r){ double s=0; for (int g=0;g<4;++g) s+=K[r][g]*yb[g]; e[oB+r]=s; }
        for (int r=0;r<6;++r) for (int c=0;c<6;++c){
            double s=P[r][c]; for (int g=0;g<4;++g) s-=K[r][g]*PH[c][g];
            e[oC+r*6+c]=s;
        }
        for (int r=0;r<6;++r) for (int c=r+1;c<6;++c){
            double m=0.5*(e[oC+r*6+c]+e[oC+c*6+r]); e[oC+r*6+c]=m; e[oC+c*6+r]=m; }
        for (int i=0;i<6;++i) e[oE+i]=0.0;
        for (int i=0;i<36;++i) e[oJ+i]=0.0;
    } else {
        double S4[4][4];
        for (int g=0;g<4;++g) for (int h=0;h<4;++h)
            S4[g][h]=Qs[g>>1][h>>1]+((g==h)?rn:0.0);
        double Si[4][4]; inv4d(S4,Si);
        double K2[2][4];
        for (int i=0;i<2;++i) for (int g=0;g<4;++g){
            double s=0; for (int h=0;h<4;++h) s+=Qs[i][h>>1]*Si[h][g]; K2[i][g]=s; }
        double A[6][6];
        for (int r=0;r<6;++r) for (int c=0;c<6;++c) A[r][c]=(r==c)?1.0:0.0;
        A[4][5]=1.0;
        for (int i=0;i<2;++i){
            for (int g=0;g<4;++g) A[4+i][g]-=K2[i][g];
            double s4=K2[i][0]+K2[i][1];
            double s5=s4+K2[i][2]+K2[i][3];
            A[4+i][4]-=s4; A[4+i][5]-=s5;
        }
        double C2[2][2];
        for (int i=0;i<2;++i) for (int j=0;j<2;++j){
            double s=Qs[i][j];
            for (int g=0;g<4;++g) s-=K2[i][g]*Qs[g>>1][j];
            C2[i][j]=s;
        }
        { double m=0.5*(C2[0][1]+C2[1][0]); C2[0][1]=m; C2[1][0]=m; }
        for (int r=0;r<6;++r) e[oB+r]=0.0;
        for (int i=0;i<2;++i){ double s=0; for (int g=0;g<4;++g) s+=K2[i][g]*yb[g]; e[oB+4+i]=s; }
        double u[4];
        for (int g=0;g<4;++g){ double s=0; for (int h=0;h<4;++h) s+=Si[g][h]*yb[h]; u[g]=s; }
        for (int c=0;c<4;++c) e[oE+c]=u[c];
        e[oE+4]=u[0]+u[1]; e[oE+5]=u[0]+u[1]+u[2]+u[3];
        double V[4][6];
        for (int g=0;g<4;++g){
            for (int d=0;d<4;++d) V[g][d]=Si[g][d];
            V[g][4]=Si[g][0]+Si[g][1];
            V[g][5]=Si[g][0]+Si[g][1]+Si[g][2]+Si[g][3];
        }
        double J[6][6];
        for (int c=0;c<4;++c) for (int d=0;d<6;++d) J[c][d]=V[c][d];
        for (int d=0;d<6;++d){ J[4][d]=V[0][d]+V[1][d]; J[5][d]=V[0][d]+V[1][d]+V[2][d]+V[3][d]; }
        for (int r=0;r<6;++r) for (int c=0;c<6;++c) e[oA+r*6+c]=A[r][c];
        for (int i=0;i<36;++i) e[oC+i]=0.0;
        e[oC+4*6+4]=C2[0][0]; e[oC+4*6+5]=C2[0][1];
        e[oC+5*6+4]=C2[1][0]; e[oC+5*6+5]=C2[1][1];
        for (int r=0;r<6;++r) for (int c=0;c<6;++c) e[oJ+r*6+c]=J[r][c];
    }
}

__global__ void scan_level(int d, int srcp) {
    int i = blockIdx.x*blockDim.x + threadIdx.x;
    if (i >= TS) return;
    const double* src = g_buf[srcp];
    double* dst = g_buf[srcp^1];
    if (i < d) {
        for (int k=0;k<120;++k) dst[i*ESTR+k]=src[i*ESTR+k];
    } else {
        compose(&src[(i-d)*ESTR], &src[i*ESTR], &dst[i*ESTR]);
    }
}

__global__ void ll_terms(const float* __restrict__ track, const float* __restrict__ bs,
                         const float* __restrict__ onp, const float* __restrict__ tnp, int finp) {
    int t = blockIdx.x*blockDim.x + threadIdx.x;
    const double sig2 = (double)onp[0]*(double)onp[0];
    const double q = (double)tnp[0]*(double)tnp[0];
    const double rn = sig2/32.0;
    double llt = 0.0;
    if (t < TS) {
        double m[6], P[6][6];
        if (t == 0) {
            for (int i=0;i<6;++i) m[i]=0.0;
            for (int r=0;r<6;++r) for (int c=0;c<6;++c) P[r][c]=0.0;
            P[0][0]=(double)bs[0]/32.0; P[1][1]=(double)bs[1]/32.0;
            P[2][2]=P[0][0]; P[3][3]=P[1][1]; P[4][4]=1.0; P[5][5]=1.0;
        } else {
            const double* e = &g_buf[finp][(t-1)*ESTR];
            for (int i=0;i<6;++i) m[i]=e[oB+i];
            for (int r=0;r<6;++r) for (int c=0;c<6;++c) P[r][c]=e[oC+r*6+c];
        }
        double mp[6];
        for (int i=0;i<4;++i) mp[i]=m[i];
        mp[4]=m[4]+m[5]; mp[5]=m[5];
        for (int c=0;c<6;++c) P[4][c]+=P[5][c];
        for (int r=0;r<6;++r) P[r][4]+=P[r][5];
        P[4][4]+=q/3.0; P[4][5]+=q*0.5; P[5][4]+=q*0.5; P[5][5]+=q;
        double y0=(double)track[2*t], y1=(double)track[2*t+1];
        double yb[4]={y0,y1,y0,y1};
        double S4[4][4], v[4];
        for (int g=0;g<4;++g){
            int rg=g>>1;
            v[g]=yb[g]-(mp[g]+mp[4+rg]);
            for (int h=0;h<4;++h){
                int rh=h>>1;
                S4[g][h]=P[g][h]+P[g][4+rh]+P[4+rg][h]+P[4+rg][4+rh]+((g==h)?rn:0.0);
            }
        }
        double Si[4][4];
        double det=inv4d(S4,Si);
        double quad=0.0;
        for (int g=0;g<4;++g) for (int h=0;h<4;++h) quad+=v[g]*Si[g][h]*v[h];
        double tf=(double)t;
        double d0=1.0/(1.0/(double)bs[0]+tf/sig2)+sig2;
        double d1=1.0/(1.0/(double)bs[1]+tf/sig2)+sig2;
        double step=128.0*LOG2PI + 62.0*(log(d0)+log(d1))
                  + 4.0*log(32.0) + log(det) + quad;
        llt = -0.5*step;
    }
    __shared__ double sd[128];
    sd[threadIdx.x]=llt; __syncthreads();
    for (int s=64;s>0;s>>=1){ if((int)threadIdx.x<s) sd[threadIdx.x]+=sd[threadIdx.x+s]; __syncthreads(); }
    if (threadIdx.x==0) g_llp[blockIdx.x]=sd[0];
}

__global__ void __launch_bounds__(256)
finalize(const float* __restrict__ bs, const float* __restrict__ onp,
         const float* __restrict__ tnp,
         float* __restrict__ out, int out_size, int finp) {
    __shared__ double sLam4[4], sPhi[4][4], sE[4][2], sSsInv[2][2], sPu[3];
    __shared__ double sll;
    if (threadIdx.x == 0) {
        const double sig2 = (double)onp[0]*(double)onp[0];
        const double q = (double)tnp[0]*(double)tnp[0];
        double ll=0.0;
        for (int i=0;i<16;++i) ll+=g_llp[i];
        sll=ll;
        const double* e = &g_buf[finp][(TS-1)*ESTR];
        double P6[6][6];
        for (int r=0;r<6;++r) for (int c=0;c<6;++c) P6[r][c]=e[oC+r*6+c];
        double aT0=1.0/(1.0/(double)bs[0]+2048.0/sig2);
        double aT1=1.0/(1.0/(double)bs[1]+2048.0/sig2);
        double a[4]={aT0,aT1,aT0,aT1};
        double B[4][4], C[4][2];
        for (int g=0;g<4;++g){
            for (int h=0;h<4;++h) B[g][h]=P6[g][h]-((g==h)?a[g]/32.0:0.0);
            C[g][0]=P6[g][4]; C[g][1]=P6[g][5];
        }
        double p00=P6[4][4], p02=P6[4][5], p22=P6[5][5];
        double La[4]={1.0/a[0],1.0/a[1],1.0/a[2],1.0/a[3]};
        double Xb[4][4];
        for (int g=0;g<4;++g) for (int h=0;h<4;++h)
            Xb[g][h]=((g==h)?1.0:0.0)+32.0*La[g]*B[g][h];
        double Yb[4][4]; inv4d(Xb,Yb);
        double G[4][4];
        for (int g=0;g<4;++g) for (int h=0;h<4;++h){
            double s=0; for (int k=0;k<4;++k) s+=B[g][k]*Yb[k][h];
            G[g][h]=La[g]*s*La[h];
        }
        double M4[4][4];
        for (int g=0;g<4;++g) for (int h=0;h<4;++h)
            M4[g][h]=((g==h)?La[g]:0.0)-32.0*G[g][h];
        double MC[4][2];
        for (int g=0;g<4;++g){
            double t0=0,t1=0;
            for (int k=0;k<4;++k){ t0+=M4[g][k]*C[k][0]; t1+=M4[g][k]*C[k][1]; }
            MC[g][0]=t0; MC[g][1]=t1;
        }
        double ss00=p00, ss01=p02, ss11=p22;
        for (int g=0;g<4;++g){
            ss00-=32.0*C[g][0]*MC[g][0];
            ss01-=32.0*C[g][0]*MC[g][1];
            ss11-=32.0*C[g][1]*MC[g][1];
        }
        {
            double det=ss00*ss11-ss01*ss01;
            double id=1.0/det;
            sSsInv[0][0]=ss11*id; sSsInv[0][1]=-ss01*id;
            sSsInv[1][0]=-ss01*id; sSsInv[1][1]=ss00*id;
        }
        for (int g=0;g<4;++g){
            sE[g][0]=-(MC[g][0]*sSsInv[0][0]+MC[g][1]*sSsInv[1][0]);
            sE[g][1]=-(MC[g][0]*sSsInv[0][1]+MC[g][1]*sSsInv[1][1]);
        }
        for (int g=0;g<4;++g) for (int h=0;h<4;++h)
            sPhi[g][h]=-G[g][h]-(sE[g][0]*MC[h][0]+sE[g][1]*MC[h][1]);
        for (int g=0;g<4;++g) sLam4[g]=La[g];
        {
            const double td=2048.0;
            double sum00=td/3.0+td*(td-1.0)/2.0+(td-1.0)*td*(2.0*td-1.0)/6.0;
            double sum01=td/2.0+td*(td-1.0)/2.0;
            double pu00=1.0+td*td+q*sum00;
            double pu01=td+q*sum01;
            double pu11=1.0+q*td;
            double det=pu00*pu11-pu01*pu01, idd=1.0/det;
            sPu[0]=pu11*idd; sPu[1]=-pu01*idd; sPu[2]=pu00*idd;
        }
    }
    __syncthreads();
    const int off = (out_size >= 17425) ? 1 : 0;
    if (threadIdx.x == 0 && off) out[0] = (float)sll;
    for (int ecnt = threadIdx.x; ecnt < 17424; ecnt += blockDim.x) {
        int r = ecnt / 132, c = ecnt % 132;
        double val = 0.0;
        if (r < 128 && c < 128) {
            int g=(r&1)+((r>=64)?2:0), h=(c&1)+((c>=64)?2:0);
            val=sPhi[g][h];
            if (r==c) val+=sLam4[g];
        } else if (r < 128) {
            int g=(r&1)+((r>=64)?2:0), j=c-128;
            if (j==0) val=sE[g][0]; else if (j==2) val=sE[g][1];
        } else if (c < 128) {
            int h=(c&1)+((c>=64)?2:0), i=r-128;
            if (i==0) val=sE[h][0]; else if (i==2) val=sE[h][1];
        } else {
            int i=r-128, j=c-128;
            if ((i==0||i==2)&&(j==0||j==2)) val=sSsInv[i>>1][j>>1];
            else if (i==1&&j==1) val=sPu[0];
            else if ((i==1&&j==3)||(i==3&&j==1)) val=sPu[1];
            else if (i==3&&j==3) val=sPu[2];
        }
        out[off+ecnt]=(float)val;
    }
}

extern "C" void kernel_launch(void* const* d_in, const int* in_sizes, int n_in,
                              void* d_out, int out_size) {
    const float* track       = (const float*)d_in[0];
    const float* bias_scales = (const float*)d_in[1];
    const float* obs_noise   = (const float*)d_in[2];
    const float* trans_noise = (const float*)d_in[3];
    float* out = (float*)d_out;
    init_elems<<<16,128>>>(track, bias_scales, obs_noise, trans_noise);
    int p = 0;
    for (int d=1; d<TS; d<<=1) { scan_level<<<16,128>>>(d, p); p^=1; }
    ll_terms<<<16,128>>>(track, bias_scales, obs_noise, trans_noise, p);
    finalize<<<1,256>>>(bias_scales, obs_noise, trans_noise, out, out_size, p);
}

// round 10
// speedup vs baseline: 2.9086x; 2.9086x over previous
#include <cuda_runtime.h>
#include <math.h>

#define TS 2048
#define ESTR 128
#define oA 0
#define oB 36
#define oC 42
#define oE 78
#define oJ 84
#define LOG2PI 1.8378770664093454836

__device__ float g_buf[2][TS*ESTR];
__device__ double g_llp[16];
__device__ double g_P6[36];

template<typename T> __device__ __forceinline__ T tabs(T x){ return x < T(0) ? -x : x; }

__device__ __forceinline__ float inv4f(const float A[4][4], float R[4][4]) {
    float a00=A[0][0],a01=A[0][1],a02=A[0][2],a03=A[0][3];
    float a10=A[1][0],a11=A[1][1],a12=A[1][2],a13=A[1][3];
    float a20=A[2][0],a21=A[2][1],a22=A[2][2],a23=A[2][3];
    float a30=A[3][0],a31=A[3][1],a32=A[3][2],a33=A[3][3];
    float s0=a00*a11-a10*a01,s1=a00*a12-a10*a02,s2=a00*a13-a10*a03;
    float s3=a01*a12-a11*a02,s4=a01*a13-a11*a03,s5=a02*a13-a12*a03;
    float c5=a22*a33-a32*a23,c4=a21*a33-a31*a23,c3=a21*a32-a31*a22;
    float c2=a20*a33-a30*a23,c1=a20*a32-a30*a22,c0=a20*a31-a30*a21;
    float det=s0*c5-s1*c4+s2*c3+s3*c2-s4*c1+s5*c0;
    float id=__fdividef(1.0f,det);
    R[0][0]=( a11*c5-a12*c4+a13*c3)*id; R[0][1]=(-a01*c5+a02*c4-a03*c3)*id;
    R[0][2]=( a31*s5-a32*s4+a33*s3)*id; R[0][3]=(-a21*s5+a22*s4-a23*s3)*id;
    R[1][0]=(-a10*c5+a12*c2-a13*c1)*id; R[1][1]=( a00*c5-a02*c2+a03*c1)*id;
    R[1][2]=(-a30*s5+a32*s2-a33*s1)*id; R[1][3]=( a20*s5-a22*s2+a23*s1)*id;
    R[2][0]=( a10*c4-a11*c2+a13*c0)*id; R[2][1]=(-a00*c4+a01*c2-a03*c0)*id;
    R[2][2]=( a30*s4-a31*s2+a33*s0)*id; R[2][3]=(-a20*s4+a21*s2-a23*s0)*id;
    R[3][0]=(-a10*c3+a11*c1-a12*c0)*id; R[3][1]=( a00*c3-a01*c1+a02*c0)*id;
    R[3][2]=(-a30*s3+a31*s1-a32*s0)*id; R[3][3]=( a20*s3-a21*s1+a22*s0)*id;
    return det;
}

__device__ __forceinline__ double inv4d(const double A[4][4], double R[4][4]) {
    double a00=A[0][0],a01=A[0][1],a02=A[0][2],a03=A[0][3];
    double a10=A[1][0],a11=A[1][1],a12=A[1][2],a13=A[1][3];
    double a20=A[2][0],a21=A[2][1],a22=A[2][2],a23=A[2][3];
    double a30=A[3][0],a31=A[3][1],a32=A[3][2],a33=A[3][3];
    double s0=a00*a11-a10*a01,s1=a00*a12-a10*a02,s2=a00*a13-a10*a03;
    double s3=a01*a12-a11*a02,s4=a01*a13-a11*a03,s5=a02*a13-a12*a03;
    double c5=a22*a33-a32*a23,c4=a21*a33-a31*a23,c3=a21*a32-a31*a22;
    double c2=a20*a33-a30*a23,c1=a20*a32-a30*a22,c0=a20*a31-a30*a21;
    double det=s0*c5-s1*c4+s2*c3+s3*c2-s4*c1+s5*c0;
    double id=1.0/det;
    R[0][0]=( a11*c5-a12*c4+a13*c3)*id; R[0][1]=(-a01*c5+a02*c4-a03*c3)*id;
    R[0][2]=( a31*s5-a32*s4+a33*s3)*id; R[0][3]=(-a21*s5+a22*s4-a23*s3)*id;
    R[1][0]=(-a10*c5+a12*c2-a13*c1)*id; R[1][1]=( a00*c5-a02*c2+a03*c1)*id;
    R[1][2]=(-a30*s5+a32*s2-a33*s1)*id; R[1][3]=( a20*s5-a22*s2+a23*s1)*id;
    R[2][0]=( a10*c4-a11*c2+a13*c0)*id; R[2][1]=(-a00*c4+a01*c2-a03*c0)*id;
    R[2][2]=( a30*s4-a31*s2+a33*s0)*id; R[2][3]=(-a20*s4+a21*s2-a23*s0)*id;
    R[3][0]=(-a10*c3+a11*c1-a12*c0)*id; R[3][1]=( a00*c3-a01*c1+a02*c0)*id;
    R[3][2]=(-a30*s3+a31*s1-a32*s0)*id; R[3][3]=( a20*s3-a21*s1+a22*s0)*id;
    return det;
}

// Row-parallel Sarkka composition: 6 lanes per composition, lane r owns row r
// of each 6x6 matrix; b,eta replicated on all lanes. ei earlier, ej later.
template<typename T, bool VEC>
__device__ __forceinline__ void compose_rp(
    unsigned mask, int base, int r,
    const T* A1, const T* C1, const T* J1, const T* b1, const T* e1,
    const T* A2, const T* C2, const T* J2, const T* b2, const T* e2,
    T* Ao, T* Co, T* Jo, T* bo, T* eo)
{
    T M[12];
#pragma unroll
    for (int c=0;c<6;++c){
        T s=(r==c)?T(1):T(0);
#pragma unroll
        for (int k=0;k<6;++k) s += C1[k]*__shfl_sync(mask, J2[c], base+k);
        M[c]=s; M[6+c]=(r==c)?T(1):T(0);
    }
    // Gauss-Jordan with partial pivoting (row-parallel)
#pragma unroll
    for (int col=0;col<6;++col){
        T v = (r>=col)?tabs(M[col]):T(-1);
        int p=col; T bv=__shfl_sync(mask, v, base+col);
#pragma unroll
        for (int rr=0;rr<6;++rr){
            T vv=__shfl_sync(mask, v, base+rr);
            if (rr>col && vv>bv){ bv=vv; p=rr; }
        }
        int src = (r==col)?p:((r==p)?col:r);
#pragma unroll
        for (int j=0;j<12;++j) M[j]=__shfl_sync(mask, M[j], base+src);
        T piv=__shfl_sync(mask, M[col], base+col);
        T ip=T(1)/piv;
        if (r==col){
#pragma unroll
            for (int j=0;j<12;++j) M[j]*=ip;
        }
        T f=M[col];
        T pr[12];
#pragma unroll
        for (int j=0;j<12;++j) pr[j]=__shfl_sync(mask, M[j], base+col);
        if (r!=col){
#pragma unroll
            for (int j=0;j<12;++j) M[j]-=f*pr[j];
        }
    }
    T D[6];
#pragma unroll
    for (int c=0;c<6;++c) D[c]=M[6+c];
    T T1[6];
#pragma unroll
    for (int c=0;c<6;++c){ T s=T(0);
#pragma unroll
        for (int k=0;k<6;++k) s+=D[k]*__shfl_sync(mask, A1[c], base+k);
        T1[c]=s; }
#pragma unroll
    for (int c=0;c<6;++c){ T s=T(0);
#pragma unroll
        for (int k=0;k<6;++k) s+=A2[k]*__shfl_sync(mask, T1[c], base+k);
        Ao[c]=s; }
    if (VEC) {
        T u[6], wv[6];
#pragma unroll
        for (int i=0;i<6;++i){ T s=b1[i];
#pragma unroll
            for (int k=0;k<6;++k) s+=__shfl_sync(mask, C1[k], base+i)*e2[k];
            u[i]=s; }
#pragma unroll
        for (int i=0;i<6;++i){ T s=T(0);
#pragma unroll
            for (int k=0;k<6;++k) s+=__shfl_sync(mask, D[k], base+i)*u[k];
            wv[i]=s; }
#pragma unroll
        for (int i=0;i<6;++i){ T s=b2[i];
#pragma unroll
            for (int k=0;k<6;++k) s+=__shfl_sync(mask, A2[k], base+i)*wv[k];
            bo[i]=s; }
        T rv[6];
#pragma unroll
        for (int k=0;k<6;++k){ T s=e2[k];
#pragma unroll
            for (int m=0;m<6;++m) s-=__shfl_sync(mask, J2[m], base+k)*b1[m];
            rv[k]=s; }
#pragma unroll
        for (int c=0;c<6;++c){ T s=e1[c];
#pragma unroll
            for (int k=0;k<6;++k) s+=__shfl_sync(mask, T1[c], base+k)*rv[k];
            eo[c]=s; }
    }
    T S[6], Tt[6];
#pragma unroll
    for (int c=0;c<6;++c){ T s=T(0);
#pragma unroll
        for (int k=0;k<6;++k) s+=D[k]*__shfl_sync(mask, C1[c], base+k);
        S[c]=s; }
#pragma unroll
    for (int c=0;c<6;++c){ T s=T(0);
#pragma unroll
        for (int k=0;k<6;++k) s+=A2[k]*__shfl_sync(mask, S[c], base+k);
        Tt[c]=s; }
#pragma unroll
    for (int c=0;c<6;++c){ T s=C2[c];
#pragma unroll
        for (int k=0;k<6;++k) s+=Tt[k]*__shfl_sync(mask, A2[k], base+c);
        Co[c]=s; }
    T T5[6];
#pragma unroll
    for (int c=0;c<6;++c){ T s=T(0);
#pragma unroll
        for (int k=0;k<6;++k) s+=J2[k]*__shfl_sync(mask, A1[c], base+k);
        T5[c]=s; }
    T T1t[6];
#pragma unroll
    for (int j=0;j<6;++j){
#pragma unroll
        for (int k=0;k<6;++k){
            T w2=__shfl_sync(mask, T1[j], base+k);
            if (r==j) T1t[k]=w2;
        }
    }
#pragma unroll
    for (int c=0;c<6;++c){ T s=J1[c];
#pragma unroll
        for (int k=0;k<6;++k) s+=T1t[k]*__shfl_sync(mask, T5[c], base+k);
        Jo[c]=s; }
}

__global__ void init_elems(const float* __restrict__ track, const float* __restrict__ bs,
                           const float* __restrict__ onp, const float* __restrict__ tnp) {
    int t = blockIdx.x*blockDim.x + threadIdx.x;
    if (t >= TS) return;
    float* e = &g_buf[0][t*ESTR];
    const float sig2 = onp[0]*onp[0];
    const float q = tnp[0]*tnp[0];
    const float rn = sig2/32.0f;
    float Qs[2][2] = {{q/3.0f, q*0.5f},{q*0.5f, q}};
    float y0 = track[2*t], y1 = track[2*t+1];
    float yb[4] = {y0,y1,y0,y1};
    if (t == 0) {
        float P[6][6];
        for (int r=0;r<6;++r) for (int c=0;c<6;++c) P[r][c]=0.0f;
        P[0][0]=bs[0]/32.0f; P[1][1]=bs[1]/32.0f;
        P[2][2]=P[0][0]; P[3][3]=P[1][1];
        P[4][4]=2.0f+Qs[0][0]; P[4][5]=1.0f+Qs[0][1];
        P[5][4]=1.0f+Qs[1][0]; P[5][5]=1.0f+Qs[1][1];
        float PH[6][4];
        for (int r=0;r<6;++r) for (int g=0;g<4;++g) PH[r][g]=P[r][g]+P[r][4+(g>>1)];
        float S4[4][4];
        for (int g=0;g<4;++g) for (int h=0;h<4;++h)
            S4[g][h]=PH[g][h]+PH[4+(g>>1)][h]+((g==h)?rn:0.0f);
        float Si[4][4]; inv4f(S4,Si);
        float K[6][4];
        for (int r=0;r<6;++r) for (int g=0;g<4;++g){
            float s=0; for (int h=0;h<4;++h) s+=PH[r][h]*Si[h][g]; K[r][g]=s; }
        for (int i=0;i<36;++i) e[oA+i]=0.0f;
        for (int r=0;r<6;++r){ float s=0; for (int g=0;g<4;++g) s+=K[r][g]*yb[g]; e[oB+r]=s; }
        for (int r=0;r<6;++r) for (int c=0;c<6;++c){
            float s=P[r][c]; for (int g=0;g<4;++g) s-=K[r][g]*PH[c][g];
            e[oC+r*6+c]=s;
        }
        for (int r=0;r<6;++r) for (int c=r+1;c<6;++c){
            float m=0.5f*(e[oC+r*6+c]+e[oC+c*6+r]); e[oC+r*6+c]=m; e[oC+c*6+r]=m; }
        for (int i=0;i<6;++i) e[oE+i]=0.0f;
        for (int i=0;i<36;++i) e[oJ+i]=0.0f;
    } else {
        float S4[4][4];
        for (int g=0;g<4;++g) for (int h=0;h<4;++h)
            S4[g][h]=Qs[g>>1][h>>1]+((g==h)?rn:0.0f);
        float Si[4][4]; inv4f(S4,Si);
        float K2[2][4];
        for (int i=0;i<2;++i) for (int g=0;g<4;++g){
            float s=0; for (int h=0;h<4;++h) s+=Qs[i][h>>1]*Si[h][g]; K2[i][g]=s; }
        float A[6][6];
        for (int r=0;r<6;++r) for (int c=0;c<6;++c) A[r][c]=(r==c)?1.0f:0.0f;
        A[4][5]=1.0f;
        for (int i=0;i<2;++i){
            for (int g=0;g<4;++g) A[4+i][g]-=K2[i][g];
            float s4=K2[i][0]+K2[i][1];
            float s5=s4+K2[i][2]+K2[i][3];
            A[4+i][4]-=s4; A[4+i][5]-=s5;
        }
        float C2[2][2];
        for (int i=0;i<2;++i) for (int j=0;j<2;++j){
            float s=Qs[i][j];
            for (int g=0;g<4;++g) s-=K2[i][g]*Qs[g>>1][j];
            C2[i][j]=s;
        }
        { float m=0.5f*(C2[0][1]+C2[1][0]); C2[0][1]=m; C2[1][0]=m; }
        for (int r=0;r<6;++r) e[oB+r]=0.0f;
        for (int i=0;i<2;++i){ float s=0; for (int g=0;g<4;++g) s+=K2[i][g]*yb[g]; e[oB+4+i]=s; }
        float u[4];
        for (int g=0;g<4;++g){ float s=0; for (int h=0;h<4;++h) s+=Si[g][h]*yb[h]; u[g]=s; }
        for (int c=0;c<4;++c) e[oE+c]=u[c];
        e[oE+4]=u[0]+u[1]; e[oE+5]=u[0]+u[1]+u[2]+u[3];
        float V[4][6];
        for (int g=0;g<4;++g){
            for (int d=0;d<4;++d) V[g][d]=Si[g][d];
            V[g][4]=Si[g][0]+Si[g][1];
            V[g][5]=Si[g][0]+Si[g][1]+Si[g][2]+Si[g][3];
        }
        float J[6][6];
        for (int c=0;c<4;++c) for (int d=0;d<6;++d) J[c][d]=V[c][d];
        for (int d=0;d<6;++d){ J[4][d]=V[0][d]+V[1][d]; J[5][d]=V[0][d]+V[1][d]+V[2][d]+V[3][d]; }
        for (int r=0;r<6;++r) for (int c=0;c<6;++c) e[oA+r*6+c]=A[r][c];
        for (int i=0;i<36;++i) e[oC+i]=0.0f;
        e[oC+4*6+4]=C2[0][0]; e[oC+4*6+5]=C2[0][1];
        e[oC+5*6+4]=C2[1][0]; e[oC+5*6+5]=C2[1][1];
        for (int r=0;r<6;++r) for (int c=0;c<6;++c) e[oJ+r*6+c]=J[r][c];
    }
}

__global__ void __launch_bounds__(256) scan_level(int d, int srcp) {
    int lane = threadIdx.x & 31;
    int warp = threadIdx.x >> 5;
    if (lane >= 30) return;
    int g = lane/6, r = lane - g*6, base = g*6;
    unsigned mask = 0x3Fu << base;
    int gid = (blockIdx.x*8 + warp)*5 + g;
    if (gid >= TS) return;
    const float* sb = g_buf[srcp];
    float* db = g_buf[srcp^1];
    const float* ej = &sb[gid*ESTR];
    float* dst = &db[gid*ESTR];
    if (gid < d) {
#pragma unroll
        for (int j=0;j<20;++j) dst[r*20+j]=ej[r*20+j];
        return;
    }
    const float* ei = &sb[(gid-d)*ESTR];
    float A1[6],C1[6],J1[6],b1[6],e1[6],A2[6],C2[6],J2[6],b2[6],e2[6];
#pragma unroll
    for (int k=0;k<6;++k){
        A1[k]=ei[oA+r*6+k]; C1[k]=ei[oC+r*6+k]; J1[k]=ei[oJ+r*6+k];
        A2[k]=ej[oA+r*6+k]; C2[k]=ej[oC+r*6+k]; J2[k]=ej[oJ+r*6+k];
        b1[k]=ei[oB+k]; e1[k]=ei[oE+k]; b2[k]=ej[oB+k]; e2[k]=ej[oE+k];
    }
    float Ao[6],Co[6],Jo[6],bo[6],eoo[6];
    compose_rp<float,true>(mask,base,r,A1,C1,J1,b1,e1,A2,C2,J2,b2,e2,Ao,Co,Jo,bo,eoo);
#pragma unroll
    for (int k=0;k<6;++k){ dst[oA+r*6+k]=Ao[k]; dst[oC+r*6+k]=Co[k]; dst[oJ+r*6+k]=Jo[k]; }
    if (r==0){
#pragma unroll
        for (int k=0;k<6;++k){ dst[oB+k]=bo[k]; dst[oE+k]=eoo[k]; }
    }
}

__global__ void ll_terms(const float* __restrict__ track, const float* __restrict__ bs,
                         const float* __restrict__ onp, const float* __restrict__ tnp, int finp) {
    int t = blockIdx.x*blockDim.x + threadIdx.x;
    const double sig2 = (double)onp[0]*(double)onp[0];
    const double q = (double)tnp[0]*(double)tnp[0];
    const double rn = sig2/32.0;
    double llt = 0.0;
    if (t < TS) {
        double m[6], P[6][6];
        if (t == 0) {
            for (int i=0;i<6;++i) m[i]=0.0;
            for (int r=0;r<6;++r) for (int c=0;c<6;++c) P[r][c]=0.0;
            P[0][0]=(double)bs[0]/32.0; P[1][1]=(double)bs[1]/32.0;
            P[2][2]=P[0][0]; P[3][3]=P[1][1]; P[4][4]=1.0; P[5][5]=1.0;
        } else {
            const float* e = &g_buf[finp][(t-1)*ESTR];
            for (int i=0;i<6;++i) m[i]=(double)e[oB+i];
            for (int r=0;r<6;++r) for (int c=0;c<6;++c) P[r][c]=(double)e[oC+r*6+c];
        }
        double mp[6];
        for (int i=0;i<4;++i) mp[i]=m[i];
        mp[4]=m[4]+m[5]; mp[5]=m[5];
        for (int c=0;c<6;++c) P[4][c]+=P[5][c];
        for (int r=0;r<6;++r) P[r][4]+=P[r][5];
        P[4][4]+=q/3.0; P[4][5]+=q*0.5; P[5][4]+=q*0.5; P[5][5]+=q;
        double y0=(double)track[2*t], y1=(double)track[2*t+1];
        double yb[4]={y0,y1,y0,y1};
        double S4[4][4], v[4];
        for (int g=0;g<4;++g){
            int rg=g>>1;
            v[g]=yb[g]-(mp[g]+mp[4+rg]);
            for (int h=0;h<4;++h){
                int rh=h>>1;
                S4[g][h]=P[g][h]+P[g][4+rh]+P[4+rg][h]+P[4+rg][4+rh]+((g==h)?rn:0.0);
            }
        }
        double Si[4][4];
        double det=inv4d(S4,Si);
        double quad=0.0;
        for (int g=0;g<4;++g) for (int h=0;h<4;++h) quad+=v[g]*Si[g][h]*v[h];
        double tf=(double)t;
        double d0=1.0/(1.0/(double)bs[0]+tf/sig2)+sig2;
        double d1=1.0/(1.0/(double)bs[1]+tf/sig2)+sig2;
        double step=128.0*LOG2PI + 62.0*(log(d0)+log(d1))
                  + 4.0*log(32.0) + log(det) + quad;
        llt = -0.5*step;
    }
    __shared__ double sd[128];
    sd[threadIdx.x]=llt; __syncthreads();
    for (int s=64;s>0;s>>=1){ if((int)threadIdx.x<s) sd[threadIdx.x]+=sd[threadIdx.x+s]; __syncthreads(); }
    if (threadIdx.x==0) g_llp[blockIdx.x]=sd[0];
}

// fp64 covariance via binary powering: P_k=E^(2^k), R_k=E^(2^k - 1);
// P<-P*P, R<-R*P (parallel in 2 warps). After 11 iters R=E^2047; final=e0*R.
__global__ void __launch_bounds__(64) cov_power(const float* __restrict__ bs,
                                                const float* __restrict__ onp,
                                                const float* __restrict__ tnp) {
    __shared__ double sp[108], sr[108];
    int lane = threadIdx.x & 31;
    int w = threadIdx.x >> 5;
    const unsigned mask = 0x3Fu;
    const double sig2 = (double)onp[0]*(double)onp[0];
    const double q = (double)tnp[0]*(double)tnp[0];
    const double rn = sig2/32.0;
    double Qs[2][2]={{q/3.0,q*0.5},{q*0.5,q}};
    if (w==0 && lane<6) {
        int r=lane;
        double S4[4][4],Si[4][4];
        for (int g=0;g<4;++g) for (int h=0;h<4;++h)
            S4[g][h]=Qs[g>>1][h>>1]+((g==h)?rn:0.0);
        inv4d(S4,Si);
        double K2[2][4];
        for (int i=0;i<2;++i) for (int g=0;g<4;++g){
            double s=0; for (int h=0;h<4;++h) s+=Qs[i][h>>1]*Si[h][g]; K2[i][g]=s; }
        double Ar[6];
#pragma unroll
        for (int c=0;c<6;++c) Ar[c]=(r==c)?1.0:0.0;
        if (r==4) Ar[5]=1.0;
        if (r>=4){
            int i=r-4;
            for (int gg=0; gg<4; ++gg) Ar[gg]-=K2[i][gg];
            double s4=K2[i][0]+K2[i][1], s5=s4+K2[i][2]+K2[i][3];
            Ar[4]-=s4; Ar[5]-=s5;
        }
        double C2m[2][2];
        for (int i=0;i<2;++i) for (int j=0;j<2;++j){
            double s=Qs[i][j];
            for (int g=0;g<4;++g) s-=K2[i][g]*Qs[g>>1][j];
            C2m[i][j]=s;
        }
        { double m=0.5*(C2m[0][1]+C2m[1][0]); C2m[0][1]=m; C2m[1][0]=m; }
        double Cr[6]={0,0,0,0,0,0};
        if (r>=4){ Cr[4]=C2m[r-4][0]; Cr[5]=C2m[r-4][1]; }
        double V[4][6];
        for (int g=0;g<4;++g){
            for (int d=0;d<4;++d) V[g][d]=Si[g][d];
            V[g][4]=Si[g][0]+Si[g][1];
            V[g][5]=V[g][4]+Si[g][2]+Si[g][3];
        }
        double Jr[6];
#pragma unroll
        for (int c=0;c<6;++c){
            double s=0;
            for (int gg=0; gg<4; ++gg) if (r==gg) s=V[gg][c];
            if (r==4) s=V[0][c]+V[1][c];
            if (r==5) s=V[0][c]+V[1][c]+V[2][c]+V[3][c];
            Jr[c]=s;
        }
#pragma unroll
        for (int c=0;c<6;++c){
            sp[r*6+c]=Ar[c]; sp[36+r*6+c]=Cr[c]; sp[72+r*6+c]=Jr[c];
            sr[r*6+c]=(r==c)?1.0:0.0; sr[36+r*6+c]=0.0; sr[72+r*6+c]=0.0;
        }
    }
    __syncthreads();
    double dm[6];
    for (int it=0; it<11; ++it) {
        double A1[6],C1[6],J1[6],A2[6],C2[6],J2[6],Ao[6],Co[6],Jo[6];
        if (lane<6) {
            int r=lane;
            const double* eb = (w==0)? sp : sr;
#pragma unroll
            for (int k=0;k<6;++k){
                A1[k]=eb[r*6+k]; C1[k]=eb[36+r*6+k]; J1[k]=eb[72+r*6+k];
                A2[k]=sp[r*6+k]; C2[k]=sp[36+r*6+k]; J2[k]=sp[72+r*6+k];
            }
        }
        __syncthreads();
        if (lane<6) {
            int r=lane;
            compose_rp<double,false>(mask,0,r,A1,C1,J1,dm,dm,A2,C2,J2,dm,dm,Ao,Co,Jo,dm,dm);
            double* ob = (w==0)? sp : sr;
#pragma unroll
            for (int k=0;k<6;++k){ ob[r*6+k]=Ao[k]; ob[36+r*6+k]=Co[k]; ob[72+r*6+k]=Jo[k]; }
        }
        __syncthreads();
    }
    // final: e0 (earlier) composed with R
    if (w==0 && lane<6) {
        int r=lane;
        double P[36];
#pragma unroll
        for (int i=0;i<36;++i) P[i]=0.0;
        P[0]=(double)bs[0]/32.0; P[7]=(double)bs[1]/32.0;
        P[14]=P[0]; P[21]=P[7];
        P[4*6+4]=2.0+Qs[0][0]; P[4*6+5]=1.0+Qs[0][1];
        P[5*6+4]=1.0+Qs[0][1]; P[5*6+5]=1.0+Qs[1][1];
        double PH[24];
        for (int x=0;x<6;++x) for (int g=0;g<4;++g) PH[x*4+g]=P[x*6+g]+P[x*6+4+(g>>1)];
        double S4f[4][4], Sif[4][4];
        for (int g=0;g<4;++g) for (int h=0;h<4;++h)
            S4f[g][h]=PH[g*4+h]+PH[(4+(g>>1))*4+h]+((g==h)?rn:0.0);
        inv4d(S4f,Sif);
        double Kr[4];
        for (int g=0;g<4;++g){ double s=0;
            for (int h=0;h<4;++h) s+=PH[r*4+h]*Sif[h][g]; Kr[g]=s; }
        double A1[6],C1[6],J1[6],A2[6],C2[6],J2[6],Ao[6],Co[6],Jo[6];
#pragma unroll
        for (int c=0;c<6;++c){
            double s=P[r*6+c];
            for (int g=0;g<4;++g) s-=Kr[g]*PH[c*4+g];
            C1[c]=s; A1[c]=0.0; J1[c]=0.0;
            A2[c]=sr[r*6+c]; C2[c]=sr[36+r*6+c]; J2[c]=sr[72+r*6+c];
        }
        compose_rp<double,false>(mask,0,r,A1,C1,J1,dm,dm,A2,C2,J2,dm,dm,Ao,Co,Jo,dm,dm);
#pragma unroll
        for (int c=0;c<6;++c) g_P6[r*6+c]=Co[c];
    }
}

__global__ void __launch_bounds__(256)
finalize(const float* __restrict__ bs, const float* __restrict__ onp,
         const float* __restrict__ tnp,
         float* __restrict__ out, int out_size) {
    __shared__ double sLam4[4], sPhi[4][4], sE[4][2], sSsInv[2][2], sPu[3];
    __shared__ double sll;
    if (threadIdx.x == 0) {
        const double sig2 = (double)onp[0]*(double)onp[0];
        const double q = (double)tnp[0]*(double)tnp[0];
        double ll=0.0;
        for (int i=0;i<16;++i) ll+=g_llp[i];
        sll=ll;
        double P6[6][6];
        for (int r=0;r<6;++r) for (int c=0;c<6;++c) P6[r][c]=g_P6[r*6+c];
        double aT0=1.0/(1.0/(double)bs[0]+2048.0/sig2);
        double aT1=1.0/(1.0/(double)bs[1]+2048.0/sig2);
        double a[4]={aT0,aT1,aT0,aT1};
        double B[4][4], C[4][2];
        for (int g=0;g<4;++g){
            for (int h=0;h<4;++h) B[g][h]=P6[g][h]-((g==h)?a[g]/32.0:0.0);
            C[g][0]=P6[g][4]; C[g][1]=P6[g][5];
        }
        double p00=P6[4][4], p02=P6[4][5], p22=P6[5][5];
        double La[4]={1.0/a[0],1.0/a[1],1.0/a[2],1.0/a[3]};
        double Xb[4][4];
        for (int g=0;g<4;++g) for (int h=0;h<4;++h)
            Xb[g][h]=((g==h)?1.0:0.0)+32.0*La[g]*B[g][h];
        double Yb[4][4]; inv4d(Xb,Yb);
        double G[4][4];
        for (int g=0;g<4;++g) for (int h=0;h<4;++h){
            double s=0; for (int k=0;k<4;++k) s+=B[g][k]*Yb[k][h];
            G[g][h]=La[g]*s*La[h];
        }
        double M4[4][4];
        for (int g=0;g<4;++g) for (int h=0;h<4;++h)
            M4[g][h]=((g==h)?La[g]:0.0)-32.0*G[g][h];
        double MC[4][2];
        for (int g=0;g<4;++g){
            double t0=0,t1=0;
            for (int k=0;k<4;++k){ t0+=M4[g][k]*C[k][0]; t1+=M4[g][k]*C[k][1]; }
            MC[g][0]=t0; MC[g][1]=t1;
        }
        double ss00=p00, ss01=p02, ss11=p22;
        for (int g=0;g<4;++g){
            ss00-=32.0*C[g][0]*MC[g][0];
            ss01-=32.0*C[g][0]*MC[g][1];
            ss11-=32.0*C[g][1]*MC[g][1];
        }
        {
            double det=ss00*ss11-ss01*ss01;
            double id=1.0/det;
            sSsInv[0][0]=ss11*id; sSsInv[0][1]=-ss01*id;
            sSsInv[1][0]=-ss01*id; sSsInv[1][1]=ss00*id;
        }
        for (int g=0;g<4;++g){
            sE[g][0]=-(MC[g][0]*sSsInv[0][0]+MC[g][1]*sSsInv[1][0]);
            sE[g][1]=-(MC[g][0]*sSsInv[0][1]+MC[g][1]*sSsInv[1][1]);
        }
        for (int g=0;g<4;++g) for (int h=0;h<4;++h)
            sPhi[g][h]=-G[g][h]-(sE[g][0]*MC[h][0]+sE[g][1]*MC[h][1]);
        for (int g=0;g<4;++g) sLam4[g]=La[g];
        {
            const double td=2048.0;
            double sum00=td/3.0+td*(td-1.0)/2.0+(td-1.0)*td*(2.0*td-1.0)/6.0;
            double sum01=td/2.0+td*(td-1.0)/2.0;
            double pu00=1.0+td*td+q*sum00;
            double pu01=td+q*sum01;
            double pu11=1.0+q*td;
            double det=pu00*pu11-pu01*pu01, idd=1.0/det;
            sPu[0]=pu11*idd; sPu[1]=-pu01*idd; sPu[2]=pu00*idd;
        }
    }
    __syncthreads();
    const int off = (out_size >= 17425) ? 1 : 0;
    if (threadIdx.x == 0 && off) out[0] = (float)sll;
    for (int ecnt = threadIdx.x; ecnt < 17424; ecnt += blockDim.x) {
        int r = ecnt / 132, c = ecnt % 132;
        double val = 0.0;
        if (r < 128 && c < 128) {
            int g=(r&1)+((r>=64)?2:0), h=(c&1)+((c>=64)?2:0);
            val=sPhi[g][h];
            if (r==c) val+=sLam4[g];
        } else if (r < 128) {
            int g=(r&1)+((r>=64)?2:0), j=c-128;
            if (j==0) val=sE[g][0]; else if (j==2) val=sE[g][1];
        } else if (c < 128) {
            int h=(c&1)+((c>=64)?2:0), i=r-128;
            if (i==0) val=sE[h][0]; else if (i==2) val=sE[h][1];
        } else {
            int i=r-128, j=c-128;
            if ((i==0||i==2)&&(j==0||j==2)) val=sSsInv[i>>1][j>>1];
            else if (i==1&&j==1) val=sPu[0];
            else if ((i==1&&j==3)||(i==3&&j==1)) val=sPu[1];
            else if (i==3&&j==3) val=sPu[2];
        }
        out[off+ecnt]=(float)val;
    }
}

extern "C" void kernel_launch(void* const* d_in, const int* in_sizes, int n_in,
                              void* d_out, int out_size) {
    const float* track       = (const float*)d_in[0];
    const float* bias_scales = (const float*)d_in[1];
    const float* obs_noise   = (const float*)d_in[2];
    const float* trans_noise = (const float*)d_in[3];
    float* out = (float*)d_out;
    init_elems<<<16,128>>>(track, bias_scales, obs_noise, trans_noise);
    int p = 0;
    for (int d=1; d<TS; d<<=1) { scan_level<<<52,256>>>(d, p); p^=1; }
    ll_terms<<<16,128>>>(track, bias_scales, obs_noise, trans_noise, p);
    cov_power<<<1,64>>>(bias_scales, obs_noise, trans_noise);
    finalize<<<1,256>>>(bias_scales, obs_noise, trans_noise, out, out_size);
}